// round 3
// baseline (speedup 1.0000x reference)
#include <cuda_runtime.h>

#define RES     96
#define CENTERF 48.0f
#define EPSF    1e-5f
#define CAP     (RES * RES)          // 9216 entries — overflow impossible
#define NWARPS  32                   // 1024 threads/block
#define RIM2    2209.0f              // 47^2, exact in fp32

// ---- f32x2 helpers (sm_103a packed fp32 pipe) ------------------------------
__device__ __forceinline__ unsigned long long pk2(float a, float b) {
    unsigned long long r;
    asm("mov.b64 %0, {%1, %2};" : "=l"(r) : "f"(a), "f"(b));
    return r;
}
__device__ __forceinline__ void unpk2(unsigned long long v, float& a, float& b) {
    asm("mov.b64 {%0, %1}, %2;" : "=f"(a), "=f"(b) : "l"(v));
}

// ---------------------------------------------------------------------------
// Single fused kernel.  Grid: 144 = 48 i-pairs x 3 adaptive j-windows.
// Block: 1024 threads (32 warps split the compacted source list).
//
// Phase 1: deterministic ballot compaction of positive boundary values into
//          SMEM as (-bi, -bi, bj, w) float4 (negated so di01 is a packed add).
// Phase 2: per source, per lane (2 i-rows packed in f32x2):
//            di01  = add.f32x2(fi01, e.xy)           (exact ints)
//            dj    = fj - e.z                        (exact int)
//            u     = fma(dj,dj,c00) ; v = u + dc     (dc fp64-derived)
//            den01 = fma.f32x2(di01, di01, {u,v})
//            acc{0,1} += w * rcp.approx(den{0,1})
//          ~11 issues / 7 fma-pipe / 2 MUFU per 2 terms. The 2*eps*sqrt(d2)
//          cross term of the reference is dropped (rel err <= eps/z <= 1e-5).
// Windows: J0 = 48 - w_pair places the 3 windows over the interior span;
//          all-rim windows skip; j < J0 columns are rim, written by g==0.
// Phase 3: cross-warp reduction, rim select, store.
// ---------------------------------------------------------------------------
__global__ void __launch_bounds__(1024, 1) fused_kernel(
    const float* __restrict__ b, float* __restrict__ out)
{
    extern __shared__ float4 ent[];          // CAP entries, 147456 B dynamic
    __shared__ int   cnts[RES];
    __shared__ int   offs[RES];
    __shared__ int   sK;
    __shared__ float red[NWARPS * 64];

    const int tid  = threadIdx.x;
    const int wid  = tid >> 5;
    const int lane = tid & 31;

    // ---------------- Phase 1: compaction ----------------
    {
        const int r0 = wid * 3;
        #pragma unroll
        for (int rr = 0; rr < 3; rr++) {
            const int row = r0 + rr;
            int c = 0;
            #pragma unroll
            for (int s = 0; s < 3; s++) {
                float v = b[row * RES + s * 32 + lane];
                c += __popc(__ballot_sync(0xffffffffu, v > 0.0f));
            }
            if (lane == 0) cnts[row] = c;
        }
    }
    __syncthreads();

    if (wid == 0) {  // exclusive prefix over 96 row counts
        int a0 = cnts[lane], a1 = cnts[lane + 32], a2 = cnts[lane + 64];
        int s0 = a0, s1 = a1, s2 = a2;
        #pragma unroll
        for (int d = 1; d < 32; d <<= 1) {
            int t0 = __shfl_up_sync(0xffffffffu, s0, d); if (lane >= d) s0 += t0;
            int t1 = __shfl_up_sync(0xffffffffu, s1, d); if (lane >= d) s1 += t1;
            int t2 = __shfl_up_sync(0xffffffffu, s2, d); if (lane >= d) s2 += t2;
        }
        int tot0 = __shfl_sync(0xffffffffu, s0, 31);
        s1 += tot0;
        int tot1 = __shfl_sync(0xffffffffu, s1, 31);
        s2 += tot1;
        offs[lane]      = s0 - a0;
        offs[lane + 32] = s1 - a1;
        offs[lane + 64] = s2 - a2;
        if (lane == 31) sK = s2;
    }
    __syncthreads();

    {
        const int r0 = wid * 3;
        #pragma unroll
        for (int rr = 0; rr < 3; rr++) {
            const int row = r0 + rr;
            int p = offs[row];
            #pragma unroll
            for (int s = 0; s < 3; s++) {
                const int col = s * 32 + lane;
                float v = b[row * RES + col];
                unsigned m = __ballot_sync(0xffffffffu, v > 0.0f);
                if (v > 0.0f) {
                    int pos = p + __popc(m & ((1u << lane) - 1u));
                    ent[pos] = make_float4(-(float)row, -(float)row, (float)col, v);
                }
                p += __popc(m);
            }
        }
    }
    __syncthreads();

    // ---------------- window placement ----------------
    const int p   = blockIdx.x / 3;
    const int g   = blockIdx.x % 3;
    const int i0  = 2 * p;

    const int a0i = abs(i0 - 48);
    const int a1i = abs(i0 + 1 - 48);
    const int dmin = a0i < a1i ? a0i : a1i;
    int s_ = 2208 - dmin * dmin; if (s_ < 0) s_ = 0;
    const int wmax = (int)sqrtf((float)s_) + 1;   // over-estimate: safe
    int J0 = 48 - wmax; if (J0 < 0) J0 = 0;

    const int j   = J0 + 32 * g + lane;           // may exceed 95 (guarded)
    const float fi0 = (float)i0;
    const float fj  = (float)j;

    const float dic0 = fi0 - CENTERF;
    const float dic1 = dic0 + 1.0f;
    const float djc  = fj - CENTERF;
    const float r2_0 = dic0 * dic0 + djc * djc;   // exact integer-valued
    const float r2_1 = dic1 * dic1 + djc * djc;
    const float z0 = CENTERF - sqrtf(r2_0) + EPSF;
    const float z1 = CENTERF - sqrtf(r2_1) + EPSF;
    const float c00 = fmaf(z0, z0, EPSF * EPSF);
    const float dc  = (float)(((double)z1 * (double)z1 - (double)z0 * (double)z0));

    const unsigned long long fi01 = pk2(fi0, fi0 + 1.0f);

    const bool allrim = __all_sync(0xffffffffu,
                                   (r2_0 >= RIM2) && (r2_1 >= RIM2));
    const int K = sK;
    float acc0 = 0.0f, acc1 = 0.0f;

    // ---------------- Phase 2: potential ----------------
    if (!allrim) {
        #pragma unroll 4
        for (int idx = wid; idx < K; idx += NWARPS) {
            float4 e = ent[idx];                  // broadcast LDS.128
            unsigned long long bi01 = pk2(e.x, e.y);   // adjacent regs: elided
            unsigned long long di01;
            asm("add.rn.f32x2 %0, %1, %2;" : "=l"(di01) : "l"(fi01), "l"(bi01));
            float dj = fj - e.z;
            float u  = fmaf(dj, dj, c00);
            float v  = u + dc;
            unsigned long long uv = pk2(u, v);
            unsigned long long den01;
            asm("fma.rn.f32x2 %0, %1, %2, %3;" : "=l"(den01)
                : "l"(di01), "l"(di01), "l"(uv));
            float den0, den1;
            unpk2(den01, den0, den1);
            float inv0, inv1;
            asm("rcp.approx.ftz.f32 %0, %1;" : "=f"(inv0) : "f"(den0));
            asm("rcp.approx.ftz.f32 %0, %1;" : "=f"(inv1) : "f"(den1));
            acc0 = fmaf(e.w, inv0, acc0);
            acc1 = fmaf(e.w, inv1, acc1);
        }
    }

    red[wid * 64 + lane]      = acc0;
    red[wid * 64 + 32 + lane] = acc1;
    __syncthreads();

    // ---------------- Phase 3: reduce + store ----------------
    if (tid < 64) {
        const int k = tid >> 5;                   // which of the two i-rows
        const int l = tid & 31;
        float s = 0.0f;
        #pragma unroll
        for (int w = 0; w < NWARPS; w++) s += red[w * 64 + k * 32 + l];

        const int jj = J0 + 32 * g + l;
        if (jj < RES) {
            const int ii  = i0 + k;
            const float fii = (float)ii - CENTERF;
            const float fjj = (float)jj - CENTERF;
            const float r2  = fii * fii + fjj * fjj;
            const float bv  = b[ii * RES + jj];
            out[ii * RES + jj] = (r2 >= RIM2) ? bv : s;
        }
    }

    // Rim passthrough for uncovered columns j < J0 (provably rim).
    if (g == 0 && tid < RES) {
        if (tid < J0) {
            out[i0 * RES + tid]       = b[i0 * RES + tid];
            out[(i0 + 1) * RES + tid] = b[(i0 + 1) * RES + tid];
        }
    }
}

// ---------------------------------------------------------------------------
extern "C" void kernel_launch(void* const* d_in, const int* in_sizes, int n_in,
                              void* d_out, int out_size) {
    (void)in_sizes; (void)n_in; (void)out_size;
    const float* b   = (const float*)d_in[0];
    float*       out = (float*)d_out;

    const int smem_bytes = CAP * (int)sizeof(float4);  // 147456
    cudaFuncSetAttribute(fused_kernel,
                         cudaFuncAttributeMaxDynamicSharedMemorySize, smem_bytes);

    fused_kernel<<<144, 1024, smem_bytes>>>(b, out);
}